// round 1
// baseline (speedup 1.0000x reference)
#include <cuda_runtime.h>
#include <math.h>

// Problem constants
#define S_LEN 4096
#define BATCH 4
#define EMB   512
#define TOT_S 16384           // B*S
#define NQKVH 2048            // q|k|v|h fused columns
#define NPTS  16
#define NHEAD 8

// ---------------- scratch (static device globals; no allocs allowed) ----------
__device__ float g_qkvh[(size_t)TOT_S * NQKVH];   // [M,2048]: q(0:512) k(512:1024) v(1024:1536) h(1536:2048)
__device__ float g_wcat[512 * NQKVH];             // packed [K=512, N=2048] = Wq|Wk|Wv|W1
__device__ float g_bcat[NQKVH];                   // bq|bk|bv|b1
__device__ float g_off[(size_t)TOT_S * 128];      // tanh(h@W2+b2)
__device__ int   g_idx[TOT_S * NPTS];             // sample indices
__device__ float g_attn[(size_t)TOT_S * EMB];     // attention output (pre-Wo)
__device__ int   g_vlen[BATCH];                   // valid lengths

// ---------------- pack weights/biases for the fused qkvh GEMM -----------------
__global__ void pack_kernel(const float* __restrict__ Wq, const float* __restrict__ Wk,
                            const float* __restrict__ Wv, const float* __restrict__ W1,
                            const float* __restrict__ bq, const float* __restrict__ bk,
                            const float* __restrict__ bv, const float* __restrict__ b1) {
    int i = blockIdx.x * blockDim.x + threadIdx.x;
    if (i >= 512 * NQKVH) return;
    int k = i >> 11;          // row in [0,512)
    int n = i & (NQKVH - 1);  // col in [0,2048)
    int sel = n >> 9;
    int nl  = n & 511;
    const float* W = (sel == 0) ? Wq : (sel == 1) ? Wk : (sel == 2) ? Wv : W1;
    g_wcat[i] = W[k * 512 + nl];
    if (i < NQKVH) {
        const float* bb = (sel == 0) ? bq : (sel == 1) ? bk : (sel == 2) ? bv : b1;
        g_bcat[i] = bb[nl];
    }
}

// ---------------- per-batch valid length from padding mask --------------------
__global__ void vlen_kernel(const unsigned char* __restrict__ mask) {
    __shared__ int sh[256];
    int b = blockIdx.x;
    int t = threadIdx.x;
    int s = 0;
    for (int i = t; i < S_LEN; i += 256) s += (mask[b * S_LEN + i] != 0) ? 1 : 0;
    sh[t] = s;
    __syncthreads();
    for (int o = 128; o > 0; o >>= 1) { if (t < o) sh[t] += sh[t + o]; __syncthreads(); }
    if (t == 0) {
        int v = S_LEN - sh[0];
        g_vlen[b] = v < 1 ? 1 : v;
    }
}

// ---------------- fp32 tiled GEMM: C[M,N] = act(A[M,K]@B[K,N] + bias) ---------
// BM=BN=128, BK=8, TM=TN=8, 256 threads. M,N multiples of 128; K multiple of 8.
// act: 0 = none, 2 = tanh, 3 = gelu(exact) on global cols >= 1536
__global__ __launch_bounds__(256) void sgemm_kernel(
    const float* __restrict__ A, int lda,
    const float* __restrict__ B, int ldb,
    const float* __restrict__ bias,
    float* __restrict__ C, int N, int K, int act)
{
    __shared__ float As[8][128];
    __shared__ float Bs[8][128];

    const int tid = threadIdx.x;
    const int bm = blockIdx.y * 128;
    const int bn = blockIdx.x * 128;
    const int tx = tid & 15;      // 0..15 -> cols
    const int ty = tid >> 4;      // 0..15 -> rows
    const int arow = tid >> 1;          // 0..127
    const int ak   = (tid & 1) * 4;     // 0 or 4
    const int brow = tid >> 5;          // 0..7
    const int bcol = (tid & 31) * 4;    // 0..124

    const float* Aptr = A + (size_t)(bm + arow) * lda + ak;
    const float* Bptr = B + (size_t)brow * ldb + bn + bcol;

    float acc[8][8];
#pragma unroll
    for (int i = 0; i < 8; i++)
#pragma unroll
        for (int j = 0; j < 8; j++) acc[i][j] = 0.0f;

    for (int k0 = 0; k0 < K; k0 += 8) {
        float4 av = *(const float4*)(Aptr + k0);
        float4 bv = *(const float4*)(Bptr + (size_t)k0 * ldb);
        __syncthreads();
        As[ak + 0][arow] = av.x;
        As[ak + 1][arow] = av.y;
        As[ak + 2][arow] = av.z;
        As[ak + 3][arow] = av.w;
        *(float4*)&Bs[brow][bcol] = bv;
        __syncthreads();
#pragma unroll
        for (int kk = 0; kk < 8; kk++) {
            float a[8], b[8];
            *(float4*)(a)     = *(const float4*)&As[kk][ty * 8];
            *(float4*)(a + 4) = *(const float4*)&As[kk][ty * 8 + 4];
            *(float4*)(b)     = *(const float4*)&Bs[kk][tx * 8];
            *(float4*)(b + 4) = *(const float4*)&Bs[kk][tx * 8 + 4];
#pragma unroll
            for (int i = 0; i < 8; i++)
#pragma unroll
                for (int j = 0; j < 8; j++) acc[i][j] = fmaf(a[i], b[j], acc[i][j]);
        }
    }

#pragma unroll
    for (int i = 0; i < 8; i++) {
        int row = bm + ty * 8 + i;
#pragma unroll
        for (int j4 = 0; j4 < 8; j4 += 4) {
            int col = bn + tx * 8 + j4;
            float4 r;
            r.x = acc[i][j4 + 0] + bias[col + 0];
            r.y = acc[i][j4 + 1] + bias[col + 1];
            r.z = acc[i][j4 + 2] + bias[col + 2];
            r.w = acc[i][j4 + 3] + bias[col + 3];
            if (act == 2) {
                r.x = tanhf(r.x); r.y = tanhf(r.y); r.z = tanhf(r.z); r.w = tanhf(r.w);
            } else if (act == 3 && col >= 1536) {
                r.x = 0.5f * r.x * (1.0f + erff(r.x * 0.7071067811865476f));
                r.y = 0.5f * r.y * (1.0f + erff(r.y * 0.7071067811865476f));
                r.z = 0.5f * r.z * (1.0f + erff(r.z * 0.7071067811865476f));
                r.w = 0.5f * r.w * (1.0f + erff(r.w * 0.7071067811865476f));
            }
            *(float4*)(C + (size_t)row * N + col) = r;
        }
    }
}

// ---------------- offsets -> sample indices -----------------------------------
__global__ void idx_kernel(const float* __restrict__ anchors) {
    int sg = blockIdx.x * blockDim.x + threadIdx.x;
    if (sg >= TOT_S) return;
    int b  = sg >> 12;
    int sl = sg & (S_LEN - 1);
    float pos = (float)sl;
    float minall = fmaxf(pos - 1024.0f, 0.0f);
    float pbm = (float)(g_vlen[b] - 1);
    const float* row = g_off + (size_t)sg * 128;
#pragma unroll
    for (int p = 0; p < NPTS; p++) {
        float s = 0.0f;
#pragma unroll
        for (int h = 0; h < NHEAD; h++) s += row[h * NPTS + p];
        float offv = (s * 0.125f) * 8.0f;     // mean over heads * OFFSET_SCALE
        float samp = anchors[p] * pos + offv;
        samp = fminf(fmaxf(samp, minall), pos);
        samp = fminf(samp, pbm);
        g_idx[sg * NPTS + p] = __float2int_rn(samp);   // round-half-to-even, like jnp.round
    }
}

// ---------------- deformable attention ----------------------------------------
// one block (128 threads = 4 warps) per query row
__global__ __launch_bounds__(128) void attn_kernel(const unsigned char* __restrict__ mask) {
    int sg = blockIdx.x;
    int b  = sg >> 12;
    int sl = sg & (S_LEN - 1);
    int tid  = threadIdx.x;
    int warp = tid >> 5;
    int lane = tid & 31;

    __shared__ float s_scores[NPTS];
    __shared__ int   s_idx[NPTS];
    __shared__ int   s_valid[NPTS];
    __shared__ float s_w[NPTS];

    if (tid < NPTS) {
        int i = g_idx[sg * NPTS + tid];
        s_idx[tid] = i;
        bool inv = (mask[b * S_LEN + i] != 0) || (i > sl);
        s_valid[tid] = inv ? 0 : 1;
    }
    __syncthreads();

    const float* qrow = g_qkvh + (size_t)sg * NQKVH;   // q at cols 0:512
    // each warp's lane covers float4 indices {lane + 32c : c=0..3} of the 512-dim row
    float4 qf[4];
#pragma unroll
    for (int c = 0; c < 4; c++) qf[c] = ((const float4*)qrow)[lane + 32 * c];

    // 4 points per warp: dot(q, k[idx])
#pragma unroll
    for (int pp = 0; pp < 4; pp++) {
        int p = warp * 4 + pp;
        const float* krow = g_qkvh + (size_t)(b * S_LEN + s_idx[p]) * NQKVH + 512;
        float acc = 0.0f;
#pragma unroll
        for (int c = 0; c < 4; c++) {
            float4 kf = ((const float4*)krow)[lane + 32 * c];
            acc = fmaf(qf[c].x, kf.x, acc);
            acc = fmaf(qf[c].y, kf.y, acc);
            acc = fmaf(qf[c].z, kf.z, acc);
            acc = fmaf(qf[c].w, kf.w, acc);
        }
#pragma unroll
        for (int o = 16; o > 0; o >>= 1) acc += __shfl_xor_sync(0xFFFFFFFFu, acc, o);
        if (lane == 0) s_scores[p] = acc * 0.04419417382415922f;   // 1/sqrt(512)
    }
    __syncthreads();

    if (tid < NPTS) {
        float mx = -3.402823466e38f;
        int nv = 0;
        for (int q = 0; q < NPTS; q++)
            if (s_valid[q]) { mx = fmaxf(mx, s_scores[q]); nv++; }
        float w = 0.0f;
        if (nv > 0 && s_valid[tid]) w = expf(s_scores[tid] - mx);
        s_w[tid] = w;
    }
    __syncthreads();

    float sum = 0.0f;
#pragma unroll
    for (int p = 0; p < NPTS; p++) sum += s_w[p];
    float inv = (sum > 0.0f) ? (1.0f / sum) : 0.0f;

    // out[e] = sum_p w[p]*v[idx[p]][e] ; each thread owns one float4 (4*tid..4*tid+3)
    float4 acc = make_float4(0.f, 0.f, 0.f, 0.f);
#pragma unroll
    for (int p = 0; p < NPTS; p++) {
        float wp = s_w[p];
        const float* vrow = g_qkvh + (size_t)(b * S_LEN + s_idx[p]) * NQKVH + 1024;
        float4 vf = ((const float4*)vrow)[tid];
        acc.x = fmaf(wp, vf.x, acc.x);
        acc.y = fmaf(wp, vf.y, acc.y);
        acc.z = fmaf(wp, vf.z, acc.z);
        acc.w = fmaf(wp, vf.w, acc.w);
    }
    acc.x *= inv; acc.y *= inv; acc.z *= inv; acc.w *= inv;
    ((float4*)(g_attn + (size_t)sg * EMB))[tid] = acc;
}

// ---------------- launch -------------------------------------------------------
extern "C" void kernel_launch(void* const* d_in, const int* in_sizes, int n_in,
                              void* d_out, int out_size) {
    const float*         x       = (const float*)d_in[0];
    const unsigned char* mask    = (const unsigned char*)d_in[1];
    const float*         Wq      = (const float*)d_in[2];
    const float*         bq      = (const float*)d_in[3];
    const float*         Wk      = (const float*)d_in[4];
    const float*         bk      = (const float*)d_in[5];
    const float*         Wv      = (const float*)d_in[6];
    const float*         bv      = (const float*)d_in[7];
    const float*         Wo      = (const float*)d_in[8];
    const float*         bo      = (const float*)d_in[9];
    const float*         W1      = (const float*)d_in[10];
    const float*         b1      = (const float*)d_in[11];
    const float*         W2      = (const float*)d_in[12];
    const float*         b2      = (const float*)d_in[13];
    const float*         anchors = (const float*)d_in[14];
    float* out = (float*)d_out;

    float *qkvh, *wcat, *bcat, *off, *attn;
    cudaGetSymbolAddress((void**)&qkvh, g_qkvh);
    cudaGetSymbolAddress((void**)&wcat, g_wcat);
    cudaGetSymbolAddress((void**)&bcat, g_bcat);
    cudaGetSymbolAddress((void**)&off,  g_off);
    cudaGetSymbolAddress((void**)&attn, g_attn);

    // 1) pack weights + valid lengths
    pack_kernel<<<(512 * NQKVH + 255) / 256, 256>>>(Wq, Wk, Wv, W1, bq, bk, bv, b1);
    vlen_kernel<<<BATCH, 256>>>(mask);

    // 2) fused qkvh GEMM: [16384,512] @ [512,2048], gelu on last 512 cols
    sgemm_kernel<<<dim3(NQKVH / 128, TOT_S / 128), 256>>>(
        x, EMB, wcat, NQKVH, bcat, qkvh, NQKVH, EMB, 3);

    // 3) offsets GEMM: h(@cols 1536:2048 of qkvh) @ W2 [512,128], tanh
    sgemm_kernel<<<dim3(1, TOT_S / 128), 256>>>(
        qkvh + 1536, NQKVH, W2, 128, b2, off, 128, EMB, 2);

    // 4) sample indices
    idx_kernel<<<TOT_S / 256, 256>>>(anchors);

    // 5) deformable attention
    attn_kernel<<<TOT_S, 128>>>(mask);

    // 6) output projection: attn @ Wo + bo -> d_out
    sgemm_kernel<<<dim3(EMB / 128, TOT_S / 128), 256>>>(
        attn, EMB, Wo, EMB, bo, out, EMB, EMB, 0);
}

// round 7
// speedup vs baseline: 1.3153x; 1.3153x over previous
#include <cuda_runtime.h>
#include <cuda_bf16.h>
#include <math.h>
#include <stdint.h>

#define S_LEN 4096
#define BATCH 4
#define EMB   512
#define TOT_S 16384
#define NPTS  16
#define NHEAD 8
#define KCAT  1536            // 3*512 split-concatenated K
#define LDS_K 40              // padded smem leading dim (bf16 elems) -> 80B rows

// ---------------- device-global scratch -----------------------------------------
__device__ float g_qkv[(size_t)TOT_S * 1536];       // q|k|v fp32, stride 1536
__device__ float g_h[(size_t)TOT_S * 512];          // gelu(x@W1+b1)
__device__ float g_off[(size_t)TOT_S * 128];        // tanh(h@W2+b2)
__device__ int   g_idx[TOT_S * NPTS];
__device__ int   g_vlen[BATCH];
__device__ float g_bcat[1536];
__device__ __nv_bfloat16 g_xcat[(size_t)TOT_S * KCAT];      // [hi|lo|hi]
__device__ __nv_bfloat16 g_acat[(size_t)TOT_S * KCAT];      // attn out [hi|lo|hi]
__device__ __nv_bfloat16 g_wqkv[(size_t)1536 * KCAT];       // [n][hi|hi|lo]
__device__ __nv_bfloat16 g_wo[(size_t)512 * KCAT];          // [n][hi|hi|lo]

// ---------------- PTX helpers ----------------------------------------------------
__device__ __forceinline__ uint32_t smem_u32(const void* p) {
    uint32_t a;
    asm("{ .reg .u64 t; cvta.to.shared.u64 t, %1; cvt.u32.u64 %0, t; }" : "=r"(a) : "l"(p));
    return a;
}
__device__ __forceinline__ void cp16(uint32_t s, const void* g) {
    asm volatile("cp.async.cg.shared.global [%0], [%1], 16;" :: "r"(s), "l"(g));
}
__device__ __forceinline__ void ldsm4(uint32_t* r, uint32_t addr) {
    asm volatile("ldmatrix.sync.aligned.m8n8.x4.shared.b16 {%0,%1,%2,%3}, [%4];"
                 : "=r"(r[0]), "=r"(r[1]), "=r"(r[2]), "=r"(r[3]) : "r"(addr));
}
__device__ __forceinline__ void ldsm2(uint32_t* r, uint32_t addr) {
    asm volatile("ldmatrix.sync.aligned.m8n8.x2.shared.b16 {%0,%1}, [%2];"
                 : "=r"(r[0]), "=r"(r[1]) : "r"(addr));
}
__device__ __forceinline__ void mma_bf16(float* d, const uint32_t* a, const uint32_t* b) {
    asm volatile("mma.sync.aligned.m16n8k16.row.col.f32.bf16.bf16.f32 "
                 "{%0,%1,%2,%3}, {%4,%5,%6,%7}, {%8,%9}, {%0,%1,%2,%3};"
                 : "+f"(d[0]), "+f"(d[1]), "+f"(d[2]), "+f"(d[3])
                 : "r"(a[0]), "r"(a[1]), "r"(a[2]), "r"(a[3]), "r"(b[0]), "r"(b[1]));
}

// ---------------- weight pack: transpose + bf16 split, [hi|hi|lo] along K --------
__global__ void pack_tc(const float* __restrict__ Wq, const float* __restrict__ Wk,
                        const float* __restrict__ Wv, const float* __restrict__ Wo,
                        const float* __restrict__ bq, const float* __restrict__ bk,
                        const float* __restrict__ bv) {
    int i = blockIdx.x * 256 + threadIdx.x;
    if (i >= 2048 * 512) return;
    int n = i >> 9, k = i & 511;
    float w;
    __nv_bfloat16* dst;
    if (n < 1536) {
        const float* W = (n < 512) ? Wq : ((n < 1024) ? Wk : Wv);
        w = W[k * 512 + (n & 511)];
        dst = g_wqkv + (size_t)n * KCAT;
    } else {
        w = Wo[k * 512 + (n - 1536)];
        dst = g_wo + (size_t)(n - 1536) * KCAT;
    }
    __nv_bfloat16 h = __float2bfloat16(w);
    __nv_bfloat16 l = __float2bfloat16(w - __bfloat162float(h));
    dst[k] = h; dst[512 + k] = h; dst[1024 + k] = l;
    if (i < 1536) {
        const float* bb = (i < 512) ? bq : ((i < 1024) ? bk : bv);
        g_bcat[i] = bb[i & 511];
    }
}

// ---------------- x -> [hi|lo|hi] bf16 split --------------------------------------
__global__ void cvt_split(const float* __restrict__ src) {
    int i = blockIdx.x * 256 + threadIdx.x;           // one uint2 (4 bf16) per thread
    if (i >= TOT_S * 128) return;
    float4 v = ((const float4*)src)[i];
    float vv[4] = {v.x, v.y, v.z, v.w};
    union { __nv_bfloat16 b[4]; uint2 u; } H, L;
#pragma unroll
    for (int j = 0; j < 4; j++) {
        H.b[j] = __float2bfloat16(vv[j]);
        L.b[j] = __float2bfloat16(vv[j] - __bfloat162float(H.b[j]));
    }
    int m = i >> 7, c = i & 127;
    uint2* row = (uint2*)g_xcat + (size_t)m * 384;
    row[c] = H.u; row[128 + c] = L.u; row[256 + c] = H.u;
}

// ---------------- valid length ------------------------------------------------------
__global__ void vlen_kernel(const unsigned char* __restrict__ mask) {
    __shared__ int sh[256];
    int b = blockIdx.x, t = threadIdx.x;
    int s = 0;
    for (int i = t; i < S_LEN; i += 256) s += (mask[b * S_LEN + i] != 0) ? 1 : 0;
    sh[t] = s;
    __syncthreads();
    for (int o = 128; o > 0; o >>= 1) { if (t < o) sh[t] += sh[t + o]; __syncthreads(); }
    if (t == 0) { int v = S_LEN - sh[0]; g_vlen[b] = v < 1 ? 1 : v; }
}

// ---------------- bf16 mma.sync GEMM: C[M,N]=A[M,1536]@B[N,1536]^T + bias ----------
// 128x128x32 tile, 3-stage cp.async, 8 warps (2M x 4N), warp tile 64x32.
__global__ __launch_bounds__(256) void hgemm(
    const __nv_bfloat16* __restrict__ A, const __nv_bfloat16* __restrict__ B,
    const float* __restrict__ bias, float* __restrict__ C, int ldc)
{
    extern __shared__ __nv_bfloat16 sm[];
    const int K = KCAT;
    const int tid = threadIdx.x, wid = tid >> 5, lane = tid & 31;
    const int m0 = blockIdx.y * 128, n0 = blockIdx.x * 128;
    const int wm = (wid & 1) * 64, wn = (wid >> 1) * 32;
    const uint32_t s_base = smem_u32(sm);
    const uint32_t STG = 128 * LDS_K * 2;             // bytes per A (or B) stage
    const uint32_t BOFF = 3 * STG;                    // B region offset

    float acc[4][4][4];
#pragma unroll
    for (int a = 0; a < 4; a++)
#pragma unroll
        for (int b = 0; b < 4; b++)
#pragma unroll
            for (int c = 0; c < 4; c++) acc[a][b][c] = 0.0f;

    auto load_stage = [&](int kt, int s) {
        int k0 = kt * 32;
        uint32_t as = s_base + s * STG;
        uint32_t bs = s_base + BOFF + s * STG;
#pragma unroll
        for (int i = 0; i < 2; i++) {
            int item = tid + i * 256;
            int r = item >> 2, sg = item & 3;
            uint32_t off = (uint32_t)(r * LDS_K + sg * 8) * 2;
            cp16(as + off, A + (size_t)(m0 + r) * K + k0 + sg * 8);
            cp16(bs + off, B + (size_t)(n0 + r) * K + k0 + sg * 8);
        }
        asm volatile("cp.async.commit_group;" ::: "memory");
    };

    load_stage(0, 0);
    load_stage(1, 1);

    const int NIT = K / 32;                            // 48
    for (int kt = 0; kt < NIT; kt++) {
        if (kt < NIT - 2) asm volatile("cp.async.wait_group 1;" ::: "memory");
        else              asm volatile("cp.async.wait_group 0;" ::: "memory");
        __syncthreads();
        if (kt + 2 < NIT) load_stage(kt + 2, (kt + 2) % 3);

        int s = kt % 3;
        uint32_t as = s_base + s * STG;
        uint32_t bs = s_base + BOFF + s * STG;
#pragma unroll
        for (int ks = 0; ks < 2; ks++) {
            uint32_t afr[4][4], bfr[4][2];
#pragma unroll
            for (int mi = 0; mi < 4; mi++) {
                uint32_t addr = as + (uint32_t)((wm + mi * 16 + (lane & 15)) * LDS_K
                                                + ks * 16 + (lane >> 4) * 8) * 2;
                ldsm4(afr[mi], addr);
            }
#pragma unroll
            for (int ni = 0; ni < 4; ni++) {
                int l = lane & 15;
                uint32_t addr = bs + (uint32_t)((wn + ni * 8 + (l & 7)) * LDS_K
                                                + ks * 16 + ((l >> 3) & 1) * 8) * 2;
                ldsm2(bfr[ni], addr);
            }
#pragma unroll
            for (int mi = 0; mi < 4; mi++)
#pragma unroll
                for (int ni = 0; ni < 4; ni++)
                    mma_bf16(acc[mi][ni], afr[mi], bfr[ni]);
        }
    }

    // epilogue: bias + fp32 store
    const int r0 = m0 + wm + (lane >> 2);
    const int c0 = n0 + wn + (lane & 3) * 2;
#pragma unroll
    for (int mi = 0; mi < 4; mi++) {
#pragma unroll
        for (int ni = 0; ni < 4; ni++) {
            int row = r0 + mi * 16, col = c0 + ni * 8;
            float bx = bias[col], by = bias[col + 1];
            float2 v0 = make_float2(acc[mi][ni][0] + bx, acc[mi][ni][1] + by);
            float2 v1 = make_float2(acc[mi][ni][2] + bx, acc[mi][ni][3] + by);
            *(float2*)(C + (size_t)row * ldc + col) = v0;
            *(float2*)(C + (size_t)(row + 8) * ldc + col) = v1;
        }
    }
}

// ---------------- fp32 SIMT GEMM (offsets path — bit-identical math) --------------
// act: 2 = tanh, 3 = gelu(exact)
__global__ __launch_bounds__(256, 2) void sgemm_kernel(
    const float* __restrict__ A, int lda,
    const float* __restrict__ B, int ldb,
    const float* __restrict__ bias,
    float* __restrict__ C, int N, int K, int act)
{
    __shared__ float As[8][128];
    __shared__ float Bs[8][128];

    const int tid = threadIdx.x;
    const int bm = blockIdx.y * 128;
    const int bn = blockIdx.x * 128;
    const int tx = tid & 15;
    const int ty = tid >> 4;
    const int arow = tid >> 1;
    const int ak   = (tid & 1) * 4;
    const int brow = tid >> 5;
    const int bcol = (tid & 31) * 4;

    const float* Aptr = A + (size_t)(bm + arow) * lda + ak;
    const float* Bptr = B + (size_t)brow * ldb + bn + bcol;

    float acc[8][8];
#pragma unroll
    for (int i = 0; i < 8; i++)
#pragma unroll
        for (int j = 0; j < 8; j++) acc[i][j] = 0.0f;

    for (int k0 = 0; k0 < K; k0 += 8) {
        float4 av = *(const float4*)(Aptr + k0);
        float4 bv = *(const float4*)(Bptr + (size_t)k0 * ldb);
        __syncthreads();
        As[ak + 0][arow] = av.x;
        As[ak + 1][arow] = av.y;
        As[ak + 2][arow] = av.z;
        As[ak + 3][arow] = av.w;
        *(float4*)&Bs[brow][bcol] = bv;
        __syncthreads();
#pragma unroll
        for (int kk = 0; kk < 8; kk++) {
            float a[8], b[8];
            *(float4*)(a)     = *(const float4*)&As[kk][ty * 8];
            *(float4*)(a + 4) = *(const float4*)&As[kk][ty * 8 + 4];
            *(float4*)(b)     = *(const float4*)&Bs[kk][tx * 8];
            *(float4*)(b + 4) = *(const float4*)&Bs[kk][tx * 8 + 4];
#pragma unroll
            for (int i = 0; i < 8; i++)
#pragma unroll
                for (int j = 0; j < 8; j++) acc[i][j] = fmaf(a[i], b[j], acc[i][j]);
        }
    }

#pragma unroll
    for (int i = 0; i < 8; i++) {
        int row = bm + ty * 8 + i;
#pragma unroll
        for (int j4 = 0; j4 < 8; j4 += 4) {
            int col = bn + tx * 8 + j4;
            float4 r;
            r.x = acc[i][j4 + 0] + bias[col + 0];
            r.y = acc[i][j4 + 1] + bias[col + 1];
            r.z = acc[i][j4 + 2] + bias[col + 2];
            r.w = acc[i][j4 + 3] + bias[col + 3];
            if (act == 2) {
                r.x = tanhf(r.x); r.y = tanhf(r.y); r.z = tanhf(r.z); r.w = tanhf(r.w);
            } else if (act == 3) {
                r.x = 0.5f * r.x * (1.0f + erff(r.x * 0.7071067811865476f));
                r.y = 0.5f * r.y * (1.0f + erff(r.y * 0.7071067811865476f));
                r.z = 0.5f * r.z * (1.0f + erff(r.z * 0.7071067811865476f));
                r.w = 0.5f * r.w * (1.0f + erff(r.w * 0.7071067811865476f));
            }
            *(float4*)(C + (size_t)row * N + col) = r;
        }
    }
}

// ---------------- offsets -> sample indices -----------------------------------
__global__ void idx_kernel(const float* __restrict__ anchors) {
    int sg = blockIdx.x * blockDim.x + threadIdx.x;
    if (sg >= TOT_S) return;
    int b  = sg >> 12;
    int sl = sg & (S_LEN - 1);
    float pos = (float)sl;
    float minall = fmaxf(pos - 1024.0f, 0.0f);
    float pbm = (float)(g_vlen[b] - 1);
    const float* row = g_off + (size_t)sg * 128;
#pragma unroll
    for (int p = 0; p < NPTS; p++) {
        float s = 0.0f;
#pragma unroll
        for (int h = 0; h < NHEAD; h++) s += row[h * NPTS + p];
        float offv = (s * 0.125f) * 8.0f;
        float samp = anchors[p] * pos + offv;
        samp = fminf(fmaxf(samp, minall), pos);
        samp = fminf(samp, pbm);
        g_idx[sg * NPTS + p] = __float2int_rn(samp);
    }
}

// ---------------- deformable attention ----------------------------------------
__global__ __launch_bounds__(128) void attn_kernel(const unsigned char* __restrict__ mask) {
    int sg = blockIdx.x;
    int b  = sg >> 12;
    int sl = sg & (S_LEN - 1);
    int tid  = threadIdx.x;
    int warp = tid >> 5;
    int lane = tid & 31;

    __shared__ float s_scores[NPTS];
    __shared__ int   s_idx[NPTS];
    __shared__ int   s_valid[NPTS];
    __shared__ float s_w[NPTS];

    if (tid < NPTS) {
        int i = g_idx[sg * NPTS + tid];
        s_idx[tid] = i;
        bool inv = (mask[b * S_LEN + i] != 0) || (i > sl);
        s_valid[tid] = inv ? 0 : 1;
    }
    __syncthreads();

    const float* qrow = g_qkv + (size_t)sg * 1536;
    float4 qf[4];
#pragma unroll
    for (int c = 0; c < 4; c++) qf[c] = ((const float4*)qrow)[lane + 32 * c];

#pragma unroll
    for (int pp = 0; pp < 4; pp++) {
        int p = warp * 4 + pp;
        const float* krow = g_qkv + (size_t)(b * S_LEN + s_idx[p]) * 1536 + 512;
        float acc = 0.0f;
#pragma unroll
        for (int c = 0; c < 4; c++) {
            float4 kf = ((const float4*)krow)[lane + 32 * c];
            acc = fmaf(qf[c].x, kf.x, acc);
            acc = fmaf(qf[c].y, kf.y, acc);
            acc = fmaf(qf[c].z, kf.z, acc);
            acc = fmaf(qf[c].w, kf.w, acc);
        }
#pragma unroll
        for (int o = 16; o > 0; o >>= 1) acc += __shfl_xor_sync(0xFFFFFFFFu, acc, o);
        if (lane == 0) s_scores[p] = acc * 0.04419417382415922f;
    }
    __syncthreads();

    if (tid < NPTS) {
        float mx = -3.402823466e38f;
        int nv = 0;
        for (int q = 0; q < NPTS; q++)
            if (s_valid[q]) { mx = fmaxf(mx, s_scores[q]); nv++; }
        float w = 0.0f;
        if (nv > 0 && s_valid[tid]) w = expf(s_scores[tid] - mx);
        s_w[tid] = w;
    }
    __syncthreads();

    float sum = 0.0f;
#pragma unroll
    for (int p = 0; p < NPTS; p++) sum += s_w[p];
    float inv = (sum > 0.0f) ? (1.0f / sum) : 0.0f;

    float4 acc = make_float4(0.f, 0.f, 0.f, 0.f);
#pragma unroll
    for (int p = 0; p < NPTS; p++) {
        float wp = s_w[p];
        const float* vrow = g_qkv + (size_t)(b * S_LEN + s_idx[p]) * 1536 + 1024;
        float4 vf = ((const float4*)vrow)[tid];
        acc.x = fmaf(wp, vf.x, acc.x);
        acc.y = fmaf(wp, vf.y, acc.y);
        acc.z = fmaf(wp, vf.z, acc.z);
        acc.w = fmaf(wp, vf.w, acc.w);
    }
    acc.x *= inv; acc.y *= inv; acc.z *= inv; acc.w *= inv;

    // split-bf16 output in [hi|lo|hi] K-cat layout for the Wo mma GEMM
    float vv[4] = {acc.x, acc.y, acc.z, acc.w};
    union { __nv_bfloat16 bb[4]; uint2 u; } H, L;
#pragma unroll
    for (int j = 0; j < 4; j++) {
        H.bb[j] = __float2bfloat16(vv[j]);
        L.bb[j] = __float2bfloat16(vv[j] - __bfloat162float(H.bb[j]));
    }
    uint2* row = (uint2*)g_acat + (size_t)sg * 384;
    row[tid] = H.u; row[128 + tid] = L.u; row[256 + tid] = H.u;
}

// ---------------- launch -------------------------------------------------------
extern "C" void kernel_launch(void* const* d_in, const int* in_sizes, int n_in,
                              void* d_out, int out_size) {
    const float*         x       = (const float*)d_in[0];
    const unsigned char* mask    = (const unsigned char*)d_in[1];
    const float*         Wq      = (const float*)d_in[2];
    const float*         bq      = (const float*)d_in[3];
    const float*         Wk      = (const float*)d_in[4];
    const float*         bk      = (const float*)d_in[5];
    const float*         Wv      = (const float*)d_in[6];
    const float*         bv      = (const float*)d_in[7];
    const float*         Wo      = (const float*)d_in[8];
    const float*         bo      = (const float*)d_in[9];
    const float*         W1      = (const float*)d_in[10];
    const float*         b1      = (const float*)d_in[11];
    const float*         W2      = (const float*)d_in[12];
    const float*         b2      = (const float*)d_in[13];
    const float*         anchors = (const float*)d_in[14];
    float* out = (float*)d_out;

    float *qkv, *hbuf, *off, *bcat;
    __nv_bfloat16 *xcat, *acat, *wqkv, *wo;
    cudaGetSymbolAddress((void**)&qkv,  g_qkv);
    cudaGetSymbolAddress((void**)&hbuf, g_h);
    cudaGetSymbolAddress((void**)&off,  g_off);
    cudaGetSymbolAddress((void**)&bcat, g_bcat);
    cudaGetSymbolAddress((void**)&xcat, g_xcat);
    cudaGetSymbolAddress((void**)&acat, g_acat);
    cudaGetSymbolAddress((void**)&wqkv, g_wqkv);
    cudaGetSymbolAddress((void**)&wo,   g_wo);

    const int SMEM_H = 6 * 128 * LDS_K * 2;   // 61440
    cudaFuncSetAttribute(hgemm, cudaFuncAttributeMaxDynamicSharedMemorySize, SMEM_H);

    // 1) pack weights + split x + valid lens
    pack_tc<<<(2048 * 512 + 255) / 256, 256>>>(Wq, Wk, Wv, Wo, bq, bk, bv);
    cvt_split<<<(TOT_S * 128 + 255) / 256, 256>>>(x);
    vlen_kernel<<<BATCH, 256>>>(mask);

    // 2) qkv projections: split-bf16 mma.sync GEMM, K'=1536
    hgemm<<<dim3(12, 128), 256, SMEM_H>>>(xcat, wqkv, bcat, qkv, 1536);

    // 3) offsets path in exact fp32 (bit-identical to round-1 passing run)
    sgemm_kernel<<<dim3(4, 128), 256>>>(x, EMB, W1, EMB, b1, hbuf, EMB, EMB, 3);
    sgemm_kernel<<<dim3(1, 128), 256>>>(hbuf, EMB, W2, 128, b2, off, 128, EMB, 2);
    idx_kernel<<<TOT_S / 256, 256>>>(anchors);

    // 4) deformable attention (fp32), emits split-bf16 K-cat rows
    attn_kernel<<<TOT_S, 128>>>(mask);

    // 5) output projection: split-bf16 mma.sync GEMM
    hgemm<<<dim3(4, 128), 256, SMEM_H>>>(acat, wo, bo, out, EMB);
}

// round 9
// speedup vs baseline: 1.3194x; 1.0031x over previous
#include <cuda_runtime.h>
#include <cuda_bf16.h>
#include <math.h>
#include <stdint.h>

#define S_LEN 4096
#define BATCH 4
#define EMB   512
#define TOT_S 16384
#define NPTS  16
#define NHEAD 8
#define KCAT  1536            // 3*512 split-concatenated K
#define LDS_K 40              // padded smem leading dim (bf16 elems) -> 80B rows

// ---------------- device-global scratch -----------------------------------------
__device__ float g_qkv[(size_t)TOT_S * 1536];       // q|k|v fp32, stride 1536
__device__ float g_h[(size_t)TOT_S * 512];          // gelu(x@W1+b1)
__device__ float g_off[(size_t)TOT_S * 128];        // tanh(h@W2+b2)
__device__ int   g_idx[TOT_S * NPTS];
__device__ int   g_vlen[BATCH];
__device__ float g_bcat[1536];
__device__ __nv_bfloat16 g_xcat[(size_t)TOT_S * KCAT];      // [hi|lo|hi]
__device__ __nv_bfloat16 g_acat[(size_t)TOT_S * KCAT];      // attn out [hi|lo|hi]
__device__ __nv_bfloat16 g_wqkv[(size_t)1536 * KCAT];       // [n][hi|hi|lo]
__device__ __nv_bfloat16 g_wo[(size_t)512 * KCAT];          // [n][hi|hi|lo]

// ---------------- PTX helpers ----------------------------------------------------
__device__ __forceinline__ uint32_t smem_u32(const void* p) {
    uint32_t a;
    asm("{ .reg .u64 t; cvta.to.shared.u64 t, %1; cvt.u32.u64 %0, t; }" : "=r"(a) : "l"(p));
    return a;
}
__device__ __forceinline__ void cp16(uint32_t s, const void* g) {
    asm volatile("cp.async.cg.shared.global [%0], [%1], 16;" :: "r"(s), "l"(g));
}
__device__ __forceinline__ void ldsm4(uint32_t* r, uint32_t addr) {
    asm volatile("ldmatrix.sync.aligned.m8n8.x4.shared.b16 {%0,%1,%2,%3}, [%4];"
                 : "=r"(r[0]), "=r"(r[1]), "=r"(r[2]), "=r"(r[3]) : "r"(addr));
}
__device__ __forceinline__ void ldsm2(uint32_t* r, uint32_t addr) {
    asm volatile("ldmatrix.sync.aligned.m8n8.x2.shared.b16 {%0,%1}, [%2];"
                 : "=r"(r[0]), "=r"(r[1]) : "r"(addr));
}
__device__ __forceinline__ void mma_bf16(float* d, const uint32_t* a, const uint32_t* b) {
    asm volatile("mma.sync.aligned.m16n8k16.row.col.f32.bf16.bf16.f32 "
                 "{%0,%1,%2,%3}, {%4,%5,%6,%7}, {%8,%9}, {%0,%1,%2,%3};"
                 : "+f"(d[0]), "+f"(d[1]), "+f"(d[2]), "+f"(d[3])
                 : "r"(a[0]), "r"(a[1]), "r"(a[2]), "r"(a[3]), "r"(b[0]), "r"(b[1]));
}

// ---------------- weight pack: transpose + bf16 split, [hi|hi|lo] along K --------
__global__ void pack_tc(const float* __restrict__ Wq, const float* __restrict__ Wk,
                        const float* __restrict__ Wv, const float* __restrict__ Wo,
                        const float* __restrict__ bq, const float* __restrict__ bk,
                        const float* __restrict__ bv) {
    int i = blockIdx.x * 256 + threadIdx.x;
    if (i >= 2048 * 512) return;
    int n = i >> 9, k = i & 511;
    float w;
    __nv_bfloat16* dst;
    if (n < 1536) {
        const float* W = (n < 512) ? Wq : ((n < 1024) ? Wk : Wv);
        w = W[k * 512 + (n & 511)];
        dst = g_wqkv + (size_t)n * KCAT;
    } else {
        w = Wo[k * 512 + (n - 1536)];
        dst = g_wo + (size_t)(n - 1536) * KCAT;
    }
    __nv_bfloat16 h = __float2bfloat16(w);
    __nv_bfloat16 l = __float2bfloat16(w - __bfloat162float(h));
    dst[k] = h; dst[512 + k] = h; dst[1024 + k] = l;
    if (i < 1536) {
        const float* bb = (i < 512) ? bq : ((i < 1024) ? bk : bv);
        g_bcat[i] = bb[i & 511];
    }
}

// ---------------- x -> [hi|lo|hi] bf16 split --------------------------------------
__global__ void cvt_split(const float* __restrict__ src) {
    int i = blockIdx.x * 256 + threadIdx.x;           // one uint2 (4 bf16) per thread
    if (i >= TOT_S * 128) return;
    float4 v = ((const float4*)src)[i];
    float vv[4] = {v.x, v.y, v.z, v.w};
    union { __nv_bfloat16 b[4]; uint2 u; } H, L;
#pragma unroll
    for (int j = 0; j < 4; j++) {
        H.b[j] = __float2bfloat16(vv[j]);
        L.b[j] = __float2bfloat16(vv[j] - __bfloat162float(H.b[j]));
    }
    int m = i >> 7, c = i & 127;
    uint2* row = (uint2*)g_xcat + (size_t)m * 384;
    row[c] = H.u; row[128 + c] = L.u; row[256 + c] = H.u;
}

// ---------------- valid length ------------------------------------------------------
__global__ void vlen_kernel(const unsigned char* __restrict__ mask) {
    __shared__ int sh[256];
    int b = blockIdx.x, t = threadIdx.x;
    int s = 0;
    for (int i = t; i < S_LEN; i += 256) s += (mask[b * S_LEN + i] != 0) ? 1 : 0;
    sh[t] = s;
    __syncthreads();
    for (int o = 128; o > 0; o >>= 1) { if (t < o) sh[t] += sh[t + o]; __syncthreads(); }
    if (t == 0) { int v = S_LEN - sh[0]; g_vlen[b] = v < 1 ? 1 : v; }
}

// ---------------- bf16 mma.sync GEMM: C[M,N]=A[M,1536]@B[N,1536]^T + bias ----------
// 128x128x32 tile, 3-stage cp.async, 8 warps (2M x 4N), warp tile 64x32.
__global__ __launch_bounds__(256) void hgemm(
    const __nv_bfloat16* __restrict__ A, const __nv_bfloat16* __restrict__ B,
    const float* __restrict__ bias, float* __restrict__ C, int ldc)
{
    extern __shared__ __nv_bfloat16 sm[];
    const int K = KCAT;
    const int tid = threadIdx.x, wid = tid >> 5, lane = tid & 31;
    const int m0 = blockIdx.y * 128, n0 = blockIdx.x * 128;
    const int wm = (wid & 1) * 64, wn = (wid >> 1) * 32;
    const uint32_t s_base = smem_u32(sm);
    const uint32_t STG = 128 * LDS_K * 2;             // bytes per A (or B) stage
    const uint32_t BOFF = 3 * STG;                    // B region offset

    float acc[4][4][4];
#pragma unroll
    for (int a = 0; a < 4; a++)
#pragma unroll
        for (int b = 0; b < 4; b++)
#pragma unroll
            for (int c = 0; c < 4; c++) acc[a][b][c] = 0.0f;

    auto load_stage = [&](int kt, int s) {
        int k0 = kt * 32;
        uint32_t as = s_base + s * STG;
        uint32_t bs = s_base + BOFF + s * STG;
#pragma unroll
        for (int i = 0; i < 2; i++) {
            int item = tid + i * 256;
            int r = item >> 2, sg = item & 3;
            uint32_t off = (uint32_t)(r * LDS_K + sg * 8) * 2;
            cp16(as + off, A + (size_t)(m0 + r) * K + k0 + sg * 8);
            cp16(bs + off, B + (size_t)(n0 + r) * K + k0 + sg * 8);
        }
        asm volatile("cp.async.commit_group;" ::: "memory");
    };

    load_stage(0, 0);
    load_stage(1, 1);

    const int NIT = K / 32;                            // 48
    for (int kt = 0; kt < NIT; kt++) {
        if (kt < NIT - 2) asm volatile("cp.async.wait_group 1;" ::: "memory");
        else              asm volatile("cp.async.wait_group 0;" ::: "memory");
        __syncthreads();
        if (kt + 2 < NIT) load_stage(kt + 2, (kt + 2) % 3);

        int s = kt % 3;
        uint32_t as = s_base + s * STG;
        uint32_t bs = s_base + BOFF + s * STG;
#pragma unroll
        for (int ks = 0; ks < 2; ks++) {
            uint32_t afr[4][4], bfr[4][2];
#pragma unroll
            for (int mi = 0; mi < 4; mi++) {
                uint32_t addr = as + (uint32_t)((wm + mi * 16 + (lane & 15)) * LDS_K
                                                + ks * 16 + (lane >> 4) * 8) * 2;
                ldsm4(afr[mi], addr);
            }
#pragma unroll
            for (int ni = 0; ni < 4; ni++) {
                int l = lane & 15;
                uint32_t addr = bs + (uint32_t)((wn + ni * 8 + (l & 7)) * LDS_K
                                                + ks * 16 + ((l >> 3) & 1) * 8) * 2;
                ldsm2(bfr[ni], addr);
            }
#pragma unroll
            for (int mi = 0; mi < 4; mi++)
#pragma unroll
                for (int ni = 0; ni < 4; ni++)
                    mma_bf16(acc[mi][ni], afr[mi], bfr[ni]);
        }
    }

    // epilogue: bias + fp32 store
    const int r0 = m0 + wm + (lane >> 2);
    const int c0 = n0 + wn + (lane & 3) * 2;
#pragma unroll
    for (int mi = 0; mi < 4; mi++) {
#pragma unroll
        for (int ni = 0; ni < 4; ni++) {
            int row = r0 + mi * 16, col = c0 + ni * 8;
            float bx = bias[col], by = bias[col + 1];
            float2 v0 = make_float2(acc[mi][ni][0] + bx, acc[mi][ni][1] + by);
            float2 v1 = make_float2(acc[mi][ni][2] + bx, acc[mi][ni][3] + by);
            *(float2*)(C + (size_t)row * ldc + col) = v0;
            *(float2*)(C + (size_t)(row + 8) * ldc + col) = v1;
        }
    }
}

// ---------------- fp32 SIMT GEMM (offsets path — bit-identical math) --------------
// act: 2 = tanh, 3 = gelu(exact)
__global__ __launch_bounds__(256, 2) void sgemm_kernel(
    const float* __restrict__ A, int lda,
    const float* __restrict__ B, int ldb,
    const float* __restrict__ bias,
    float* __restrict__ C, int N, int K, int act)
{
    __shared__ float As[8][128];
    __shared__ float Bs[8][128];

    const int tid = threadIdx.x;
    const int bm = blockIdx.y * 128;
    const int bn = blockIdx.x * 128;
    const int tx = tid & 15;
    const int ty = tid >> 4;
    const int arow = tid >> 1;
    const int ak   = (tid & 1) * 4;
    const int brow = tid >> 5;
    const int bcol = (tid & 31) * 4;

    const float* Aptr = A + (size_t)(bm + arow) * lda + ak;
    const float* Bptr = B + (size_t)brow * ldb + bn + bcol;

    float acc[8][8];
#pragma unroll
    for (int i = 0; i < 8; i++)
#pragma unroll
        for (int j = 0; j < 8; j++) acc[i][j] = 0.0f;

    for (int k0 = 0; k0 < K; k0 += 8) {
        float4 av = *(const float4*)(Aptr + k0);
        float4 bv = *(const float4*)(Bptr + (size_t)k0 * ldb);
        __syncthreads();
        As[ak + 0][arow] = av.x;
        As[ak + 1][arow] = av.y;
        As[ak + 2][arow] = av.z;
        As[ak + 3][arow] = av.w;
        *(float4*)&Bs[brow][bcol] = bv;
        __syncthreads();
#pragma unroll
        for (int kk = 0; kk < 8; kk++) {
            float a[8], b[8];
            *(float4*)(a)     = *(const float4*)&As[kk][ty * 8];
            *(float4*)(a + 4) = *(const float4*)&As[kk][ty * 8 + 4];
            *(float4*)(b)     = *(const float4*)&Bs[kk][tx * 8];
            *(float4*)(b + 4) = *(const float4*)&Bs[kk][tx * 8 + 4];
#pragma unroll
            for (int i = 0; i < 8; i++)
#pragma unroll
                for (int j = 0; j < 8; j++) acc[i][j] = fmaf(a[i], b[j], acc[i][j]);
        }
    }

#pragma unroll
    for (int i = 0; i < 8; i++) {
        int row = bm + ty * 8 + i;
#pragma unroll
        for (int j4 = 0; j4 < 8; j4 += 4) {
            int col = bn + tx * 8 + j4;
            float4 r;
            r.x = acc[i][j4 + 0] + bias[col + 0];
            r.y = acc[i][j4 + 1] + bias[col + 1];
            r.z = acc[i][j4 + 2] + bias[col + 2];
            r.w = acc[i][j4 + 3] + bias[col + 3];
            if (act == 2) {
                r.x = tanhf(r.x); r.y = tanhf(r.y); r.z = tanhf(r.z); r.w = tanhf(r.w);
            } else if (act == 3) {
                r.x = 0.5f * r.x * (1.0f + erff(r.x * 0.7071067811865476f));
                r.y = 0.5f * r.y * (1.0f + erff(r.y * 0.7071067811865476f));
                r.z = 0.5f * r.z * (1.0f + erff(r.z * 0.7071067811865476f));
                r.w = 0.5f * r.w * (1.0f + erff(r.w * 0.7071067811865476f));
            }
            *(float4*)(C + (size_t)row * N + col) = r;
        }
    }
}

// ---------------- offsets -> sample indices -----------------------------------
__global__ void idx_kernel(const float* __restrict__ anchors) {
    int sg = blockIdx.x * blockDim.x + threadIdx.x;
    if (sg >= TOT_S) return;
    int b  = sg >> 12;
    int sl = sg & (S_LEN - 1);
    float pos = (float)sl;
    float minall = fmaxf(pos - 1024.0f, 0.0f);
    float pbm = (float)(g_vlen[b] - 1);
    const float* row = g_off + (size_t)sg * 128;
#pragma unroll
    for (int p = 0; p < NPTS; p++) {
        float s = 0.0f;
#pragma unroll
        for (int h = 0; h < NHEAD; h++) s += row[h * NPTS + p];
        float offv = (s * 0.125f) * 8.0f;
        float samp = anchors[p] * pos + offv;
        samp = fminf(fmaxf(samp, minall), pos);
        samp = fminf(samp, pbm);
        g_idx[sg * NPTS + p] = __float2int_rn(samp);
    }
}

// ---------------- deformable attention ----------------------------------------
__global__ __launch_bounds__(128) void attn_kernel(const unsigned char* __restrict__ mask) {
    int sg = blockIdx.x;
    int b  = sg >> 12;
    int sl = sg & (S_LEN - 1);
    int tid  = threadIdx.x;
    int warp = tid >> 5;
    int lane = tid & 31;

    __shared__ float s_scores[NPTS];
    __shared__ int   s_idx[NPTS];
    __shared__ int   s_valid[NPTS];
    __shared__ float s_w[NPTS];

    if (tid < NPTS) {
        int i = g_idx[sg * NPTS + tid];
        s_idx[tid] = i;
        bool inv = (mask[b * S_LEN + i] != 0) || (i > sl);
        s_valid[tid] = inv ? 0 : 1;
    }
    __syncthreads();

    const float* qrow = g_qkv + (size_t)sg * 1536;
    float4 qf[4];
#pragma unroll
    for (int c = 0; c < 4; c++) qf[c] = ((const float4*)qrow)[lane + 32 * c];

#pragma unroll
    for (int pp = 0; pp < 4; pp++) {
        int p = warp * 4 + pp;
        const float* krow = g_qkv + (size_t)(b * S_LEN + s_idx[p]) * 1536 + 512;
        float acc = 0.0f;
#pragma unroll
        for (int c = 0; c < 4; c++) {
            float4 kf = ((const float4*)krow)[lane + 32 * c];
            acc = fmaf(qf[c].x, kf.x, acc);
            acc = fmaf(qf[c].y, kf.y, acc);
            acc = fmaf(qf[c].z, kf.z, acc);
            acc = fmaf(qf[c].w, kf.w, acc);
        }
#pragma unroll
        for (int o = 16; o > 0; o >>= 1) acc += __shfl_xor_sync(0xFFFFFFFFu, acc, o);
        if (lane == 0) s_scores[p] = acc * 0.04419417382415922f;
    }
    __syncthreads();

    if (tid < NPTS) {
        float mx = -3.402823466e38f;
        int nv = 0;
        for (int q = 0; q < NPTS; q++)
            if (s_valid[q]) { mx = fmaxf(mx, s_scores[q]); nv++; }
        float w = 0.0f;
        if (nv > 0 && s_valid[tid]) w = expf(s_scores[tid] - mx);
        s_w[tid] = w;
    }
    __syncthreads();

    float sum = 0.0f;
#pragma unroll
    for (int p = 0; p < NPTS; p++) sum += s_w[p];
    float inv = (sum > 0.0f) ? (1.0f / sum) : 0.0f;

    float4 acc = make_float4(0.f, 0.f, 0.f, 0.f);
#pragma unroll
    for (int p = 0; p < NPTS; p++) {
        float wp = s_w[p];
        const float* vrow = g_qkv + (size_t)(b * S_LEN + s_idx[p]) * 1536 + 1024;
        float4 vf = ((const float4*)vrow)[tid];
        acc.x = fmaf(wp, vf.x, acc.x);
        acc.y = fmaf(wp, vf.y, acc.y);
        acc.z = fmaf(wp, vf.z, acc.z);
        acc.w = fmaf(wp, vf.w, acc.w);
    }
    acc.x *= inv; acc.y *= inv; acc.z *= inv; acc.w *= inv;

    // split-bf16 output in [hi|lo|hi] K-cat layout for the Wo mma GEMM
    float vv[4] = {acc.x, acc.y, acc.z, acc.w};
    union { __nv_bfloat16 bb[4]; uint2 u; } H, L;
#pragma unroll
    for (int j = 0; j < 4; j++) {
        H.bb[j] = __float2bfloat16(vv[j]);
        L.bb[j] = __float2bfloat16(vv[j] - __bfloat162float(H.bb[j]));
    }
    uint2* row = (uint2*)g_acat + (size_t)sg * 384;
    row[tid] = H.u; row[128 + tid] = L.u; row[256 + tid] = H.u;
}

// ---------------- launch -------------------------------------------------------
extern "C" void kernel_launch(void* const* d_in, const int* in_sizes, int n_in,
                              void* d_out, int out_size) {
    const float*         x       = (const float*)d_in[0];
    const unsigned char* mask    = (const unsigned char*)d_in[1];
    const float*         Wq      = (const float*)d_in[2];
    const float*         bq      = (const float*)d_in[3];
    const float*         Wk      = (const float*)d_in[4];
    const float*         bk      = (const float*)d_in[5];
    const float*         Wv      = (const float*)d_in[6];
    const float*         bv      = (const float*)d_in[7];
    const float*         Wo      = (const float*)d_in[8];
    const float*         bo      = (const float*)d_in[9];
    const float*         W1      = (const float*)d_in[10];
    const float*         b1      = (const float*)d_in[11];
    const float*         W2      = (const float*)d_in[12];
    const float*         b2      = (const float*)d_in[13];
    const float*         anchors = (const float*)d_in[14];
    float* out = (float*)d_out;

    float *qkv, *hbuf, *off, *bcat;
    __nv_bfloat16 *xcat, *acat, *wqkv, *wo;
    cudaGetSymbolAddress((void**)&qkv,  g_qkv);
    cudaGetSymbolAddress((void**)&hbuf, g_h);
    cudaGetSymbolAddress((void**)&off,  g_off);
    cudaGetSymbolAddress((void**)&bcat, g_bcat);
    cudaGetSymbolAddress((void**)&xcat, g_xcat);
    cudaGetSymbolAddress((void**)&acat, g_acat);
    cudaGetSymbolAddress((void**)&wqkv, g_wqkv);
    cudaGetSymbolAddress((void**)&wo,   g_wo);

    const int SMEM_H = 6 * 128 * LDS_K * 2;   // 61440
    cudaFuncSetAttribute(hgemm, cudaFuncAttributeMaxDynamicSharedMemorySize, SMEM_H);

    // 1) pack weights + split x + valid lens
    pack_tc<<<(2048 * 512 + 255) / 256, 256>>>(Wq, Wk, Wv, Wo, bq, bk, bv);
    cvt_split<<<(TOT_S * 128 + 255) / 256, 256>>>(x);
    vlen_kernel<<<BATCH, 256>>>(mask);

    // 2) qkv projections: split-bf16 mma.sync GEMM, K'=1536
    hgemm<<<dim3(12, 128), 256, SMEM_H>>>(xcat, wqkv, bcat, qkv, 1536);

    // 3) offsets path in exact fp32 (bit-identical to round-1 passing run)
    sgemm_kernel<<<dim3(4, 128), 256>>>(x, EMB, W1, EMB, b1, hbuf, EMB, EMB, 3);
    sgemm_kernel<<<dim3(1, 128), 256>>>(hbuf, EMB, W2, 128, b2, off, 128, EMB, 2);
    idx_kernel<<<TOT_S / 256, 256>>>(anchors);

    // 4) deformable attention (fp32), emits split-bf16 K-cat rows
    attn_kernel<<<TOT_S, 128>>>(mask);

    // 5) output projection: split-bf16 mma.sync GEMM
    hgemm<<<dim3(4, 128), 256, SMEM_H>>>(acat, wo, bo, out, EMB);
}